// round 2
// baseline (speedup 1.0000x reference)
#include <cuda_runtime.h>

// Depthwise1d: out[n,c,o] = sum_i x[n,c,i] * W[c,o,i] + b[c,o]
// N=4096, C=256, K(H_IN)=64, O(H_OUT)=128, fp32.
//
// Strategy: per-channel GEMM, fp32x2 packed FMA (fma.rn.f32x2) with the
// packed lane = K dimension (even/odd k partial sums), so both x and W
// stream as natural contiguous float2 -- no transpose, exact fp32 math.

#define N_TOT  4096
#define C_TOT  256
#define K_IN   64
#define O_OUT  128
#define TILE_N 64
#define XS     66   // padded row stride (floats) for Xsh
#define WS     66   // padded row stride (floats) for Wsh

__device__ __forceinline__ void ffma2(unsigned long long& d,
                                      unsigned long long a,
                                      unsigned long long b) {
    asm("fma.rn.f32x2 %0, %1, %2, %0;" : "+l"(d) : "l"(a), "l"(b));
}

__device__ __forceinline__ float2 unpack2(unsigned long long v) {
    float2 f;
    asm("mov.b64 {%0, %1}, %2;" : "=f"(f.x), "=f"(f.y) : "l"(v));
    return f;
}

__global__ __launch_bounds__(256, 2)
void dw1d_kernel(const float* __restrict__ x,
                 const float* __restrict__ W,
                 const float* __restrict__ b,
                 float* __restrict__ out) {
    extern __shared__ float smem[];
    float* Xsh = smem;                    // TILE_N * XS floats
    float* Wsh = smem + TILE_N * XS;      // O_OUT * WS floats

    const int t  = threadIdx.x;
    const int cg = t & 15;                // col group: cols o = cg + 16*cc
    const int rg = t >> 4;                // row group: rows r0..r0+3
    const int n0 = blockIdx.x * TILE_N;
    const int c  = blockIdx.y;

    // ---- Load x tile: 64 rows x 32 float2 = 2048 float2, 8 per thread ----
    {
        const float* xbase = x + (size_t)c * K_IN;
#pragma unroll
        for (int j = 0; j < 8; ++j) {
            int idx = t + 256 * j;        // 0..2047
            int r = idx >> 5;             // row 0..63
            int q = idx & 31;             // float2 index 0..31
            float2 v = *(const float2*)(xbase + ((size_t)(n0 + r) * C_TOT) * K_IN + 2 * q);
            *(float2*)&Xsh[r * XS + 2 * q] = v;
        }
    }
    // ---- Load W tile: 128 rows x 32 float2 = 4096 float2, 16 per thread ----
    {
        const float* wbase = W + (size_t)c * O_OUT * K_IN;
#pragma unroll
        for (int j = 0; j < 16; ++j) {
            int idx = t + 256 * j;        // 0..4095
            int o = idx >> 5;             // 0..127
            int q = idx & 31;
            float2 v = *(const float2*)(wbase + (size_t)o * K_IN + 2 * q);
            *(float2*)&Wsh[o * WS + 2 * q] = v;
        }
    }
    __syncthreads();

    // ---- Compute: each thread 4 rows x 8 cols, K packed as f32x2 ----
    unsigned long long acc[4][8];
#pragma unroll
    for (int i = 0; i < 4; ++i)
#pragma unroll
        for (int cc = 0; cc < 8; ++cc)
            acc[i][cc] = 0ULL;

    const int r0 = rg * 4;

#pragma unroll 4
    for (int k2 = 0; k2 < K_IN / 2; ++k2) {
        unsigned long long xv[4], wv[8];
#pragma unroll
        for (int i = 0; i < 4; ++i)
            xv[i] = *(const unsigned long long*)&Xsh[(r0 + i) * XS + 2 * k2];
#pragma unroll
        for (int cc = 0; cc < 8; ++cc)
            wv[cc] = *(const unsigned long long*)&Wsh[(cg + 16 * cc) * WS + 2 * k2];
#pragma unroll
        for (int i = 0; i < 4; ++i)
#pragma unroll
            for (int cc = 0; cc < 8; ++cc)
                ffma2(acc[i][cc], xv[i], wv[cc]);
    }

    // ---- Epilogue: reduce the k-pair, add bias, store ----
    float bb[8];
#pragma unroll
    for (int cc = 0; cc < 8; ++cc)
        bb[cc] = b[c * O_OUT + cg + 16 * cc];

#pragma unroll
    for (int i = 0; i < 4; ++i) {
        int n = n0 + r0 + i;
        float* orow = out + ((size_t)n * C_TOT + c) * O_OUT;
#pragma unroll
        for (int cc = 0; cc < 8; ++cc) {
            float2 f = unpack2(acc[i][cc]);
            orow[cg + 16 * cc] = f.x + f.y + bb[cc];
        }
    }
}

extern "C" void kernel_launch(void* const* d_in, const int* in_sizes, int n_in,
                              void* d_out, int out_size) {
    const float* x = (const float*)d_in[0];
    const float* W = (const float*)d_in[1];
    const float* b = (const float*)d_in[2];
    float* out = (float*)d_out;

    size_t smem_bytes = (size_t)(TILE_N * XS + O_OUT * WS) * sizeof(float); // 50688
    cudaFuncSetAttribute(dw1d_kernel,
                         cudaFuncAttributeMaxDynamicSharedMemorySize,
                         (int)smem_bytes);

    dim3 grid(N_TOT / TILE_N, C_TOT);
    dw1d_kernel<<<grid, 256, smem_bytes>>>(x, W, b, out);
}

// round 3
// speedup vs baseline: 1.0279x; 1.0279x over previous
#include <cuda_runtime.h>

// Depthwise1d: out[n,c,o] = sum_i x[n,c,i] * W[c,o,i] + b[c,o]
// N=4096, C=256, K(H_IN)=64, O(H_OUT)=128, fp32.
//
// R2: per-channel GEMM, fp32x2 packed FMA; all smem traffic 128-bit
// (LDS.128 / STS.128) to halve L1 wavefront count (was the binding pipe).

#define N_TOT  4096
#define C_TOT  256
#define K_IN   64
#define O_OUT  128
#define TILE_N 64
#define XS     68   // padded row stride (floats): 272B = 17*16B (16B-aligned, swizzled)
#define WS     68

__device__ __forceinline__ void ffma2(unsigned long long& d,
                                      unsigned long long a,
                                      unsigned long long b) {
    asm("fma.rn.f32x2 %0, %1, %2, %0;" : "+l"(d) : "l"(a), "l"(b));
}

__device__ __forceinline__ float2 unpack2(unsigned long long v) {
    float2 f;
    asm("mov.b64 {%0, %1}, %2;" : "=f"(f.x), "=f"(f.y) : "l"(v));
    return f;
}

__global__ __launch_bounds__(256, 2)
void dw1d_kernel(const float* __restrict__ x,
                 const float* __restrict__ W,
                 const float* __restrict__ b,
                 float* __restrict__ out) {
    extern __shared__ float smem[];
    float* Xsh = smem;                    // TILE_N * XS floats
    float* Wsh = smem + TILE_N * XS;      // O_OUT * WS floats

    const int t  = threadIdx.x;
    const int cg = t & 15;                // col group: cols o = cg + 16*cc
    const int rg = t >> 4;                // row group: rows r0..r0+3
    const int n0 = blockIdx.x * TILE_N;
    const int c  = blockIdx.y;

    // ---- Stage x tile: 64 rows x 16 float4, 4 per thread (LDG.128/STS.128) ----
    {
        const float* xbase = x + (size_t)c * K_IN;
#pragma unroll
        for (int j = 0; j < 4; ++j) {
            int idx = t + 256 * j;        // 0..1023
            int r = idx >> 4;             // row 0..63
            int q = idx & 15;             // float4 index 0..15
            float4 v = *(const float4*)(xbase + ((size_t)(n0 + r) * C_TOT) * K_IN + 4 * q);
            *(float4*)&Xsh[r * XS + 4 * q] = v;
        }
    }
    // ---- Stage W tile: 128 rows x 16 float4, 8 per thread ----
    {
        const float* wbase = W + (size_t)c * O_OUT * K_IN;
#pragma unroll
        for (int j = 0; j < 8; ++j) {
            int idx = t + 256 * j;        // 0..2047
            int o = idx >> 4;             // 0..127
            int q = idx & 15;
            float4 v = *(const float4*)(wbase + (size_t)o * K_IN + 4 * q);
            *(float4*)&Wsh[o * WS + 4 * q] = v;
        }
    }
    __syncthreads();

    // ---- Compute: 4 rows x 8 cols per thread, k in steps of 4 (LDS.128) ----
    unsigned long long acc[4][8];
#pragma unroll
    for (int i = 0; i < 4; ++i)
#pragma unroll
        for (int cc = 0; cc < 8; ++cc)
            acc[i][cc] = 0ULL;

    const int r0 = rg * 4;

#pragma unroll 4
    for (int k4 = 0; k4 < K_IN / 4; ++k4) {
        ulonglong2 xv[4];
#pragma unroll
        for (int i = 0; i < 4; ++i)
            xv[i] = *(const ulonglong2*)&Xsh[(r0 + i) * XS + 4 * k4];

#pragma unroll
        for (int half = 0; half < 2; ++half) {
            ulonglong2 wv[4];
#pragma unroll
            for (int j = 0; j < 4; ++j) {
                int cc = half * 4 + j;
                wv[j] = *(const ulonglong2*)&Wsh[(cg + 16 * cc) * WS + 4 * k4];
            }
#pragma unroll
            for (int i = 0; i < 4; ++i)
#pragma unroll
                for (int j = 0; j < 4; ++j) {
                    ffma2(acc[i][half * 4 + j], xv[i].x, wv[j].x);
                    ffma2(acc[i][half * 4 + j], xv[i].y, wv[j].y);
                }
        }
    }

    // ---- Epilogue: reduce k-pair, add bias, store ----
    float bb[8];
#pragma unroll
    for (int cc = 0; cc < 8; ++cc)
        bb[cc] = b[c * O_OUT + cg + 16 * cc];

#pragma unroll
    for (int i = 0; i < 4; ++i) {
        int n = n0 + r0 + i;
        float* orow = out + ((size_t)n * C_TOT + c) * O_OUT;
#pragma unroll
        for (int cc = 0; cc < 8; ++cc) {
            float2 f = unpack2(acc[i][cc]);
            orow[cg + 16 * cc] = f.x + f.y + bb[cc];
        }
    }
}

extern "C" void kernel_launch(void* const* d_in, const int* in_sizes, int n_in,
                              void* d_out, int out_size) {
    const float* x = (const float*)d_in[0];
    const float* W = (const float*)d_in[1];
    const float* b = (const float*)d_in[2];
    float* out = (float*)d_out;

    size_t smem_bytes = (size_t)(TILE_N * XS + O_OUT * WS) * sizeof(float); // 52224
    cudaFuncSetAttribute(dw1d_kernel,
                         cudaFuncAttributeMaxDynamicSharedMemorySize,
                         (int)smem_bytes);

    dim3 grid(N_TOT / TILE_N, C_TOT);
    dw1d_kernel<<<grid, 256, smem_bytes>>>(x, W, b, out);
}